// round 2
// baseline (speedup 1.0000x reference)
#include <cuda_runtime.h>

// Problem constants (fixed by setup_inputs)
#define BATCH 2048
#define FDIM  2048
#define NKERN 128
#define NDIM  16
#define NCOL  (NKERN * NDIM)   // 2048

// Scratch for M = x @ W  (16 MB) — __device__ global per allocation rules
__device__ float g_M[BATCH * NCOL];

// ----------------------------------------------------------------------------
// Kernel 1: SGEMM  M[2048,2048] = x[2048,2048] @ W[2048,2048]
// 128x128 block tile, BK=16, 256 threads, 8x8 per-thread microtile,
// double-buffered shared memory with register prefetch.
// ----------------------------------------------------------------------------
__global__ __launch_bounds__(256, 2)
void mbd_sgemm_kernel(const float* __restrict__ A, const float* __restrict__ W)
{
    __shared__ __align__(16) float As[2][16][132];  // [buf][k][row], pad to 132
    __shared__ __align__(16) float Bs[2][16][132];  // [buf][k][col]

    const int tid  = threadIdx.x;
    const int bRow = blockIdx.y * 128;
    const int bCol = blockIdx.x * 128;
    const int ty   = tid >> 4;   // 0..15
    const int tx   = tid & 15;   // 0..15

    // Per-thread load coordinates (constant across tiles)
    // A: 512 float4 per tile -> 2 per thread. idx -> (row r, float4-slot kv)
    // B: 512 float4 per tile -> 2 per thread. idx -> (k-row kr, float4-col c4)
    int a_r[2], a_kv[2], b_kr[2], b_c4[2];
#pragma unroll
    for (int it = 0; it < 2; it++) {
        int idx = tid + it * 256;
        a_r[it]  = idx >> 2;
        a_kv[it] = idx & 3;
        b_kr[it] = idx >> 5;
        b_c4[it] = idx & 31;
    }

    float4 ra[2], rb[2];

    // Prefetch tile 0 into registers
#pragma unroll
    for (int it = 0; it < 2; it++) {
        ra[it] = *(const float4*)(A + (size_t)(bRow + a_r[it]) * FDIM + a_kv[it] * 4);
        rb[it] = *(const float4*)(W + (size_t)b_kr[it] * NCOL + bCol + b_c4[it] * 4);
    }
    // Store tile 0 into buffer 0
#pragma unroll
    for (int it = 0; it < 2; it++) {
        As[0][a_kv[it] * 4 + 0][a_r[it]] = ra[it].x;
        As[0][a_kv[it] * 4 + 1][a_r[it]] = ra[it].y;
        As[0][a_kv[it] * 4 + 2][a_r[it]] = ra[it].z;
        As[0][a_kv[it] * 4 + 3][a_r[it]] = ra[it].w;
        *(float4*)&Bs[0][b_kr[it]][b_c4[it] * 4] = rb[it];
    }
    __syncthreads();

    float acc[8][8];
#pragma unroll
    for (int i = 0; i < 8; i++)
#pragma unroll
        for (int j = 0; j < 8; j++) acc[i][j] = 0.0f;

    const int T = FDIM / 16;   // 128 k-tiles
    for (int t = 0; t < T; t++) {
        const int buf = t & 1;

        // Prefetch next tile into registers (overlaps with compute below)
        if (t + 1 < T) {
            const int k0 = (t + 1) * 16;
#pragma unroll
            for (int it = 0; it < 2; it++) {
                ra[it] = *(const float4*)(A + (size_t)(bRow + a_r[it]) * FDIM + k0 + a_kv[it] * 4);
                rb[it] = *(const float4*)(W + (size_t)(k0 + b_kr[it]) * NCOL + bCol + b_c4[it] * 4);
            }
        }

        // Compute on current buffer
#pragma unroll
        for (int k = 0; k < 16; k++) {
            float a[8], b[8];
            *(float4*)&a[0] = *(const float4*)&As[buf][k][ty * 8];
            *(float4*)&a[4] = *(const float4*)&As[buf][k][ty * 8 + 4];
            *(float4*)&b[0] = *(const float4*)&Bs[buf][k][tx * 8];
            *(float4*)&b[4] = *(const float4*)&Bs[buf][k][tx * 8 + 4];
#pragma unroll
            for (int i = 0; i < 8; i++)
#pragma unroll
                for (int j = 0; j < 8; j++)
                    acc[i][j] = fmaf(a[i], b[j], acc[i][j]);
        }

        // Commit prefetched tile to the other buffer
        if (t + 1 < T) {
            const int nb = buf ^ 1;
#pragma unroll
            for (int it = 0; it < 2; it++) {
                As[nb][a_kv[it] * 4 + 0][a_r[it]] = ra[it].x;
                As[nb][a_kv[it] * 4 + 1][a_r[it]] = ra[it].y;
                As[nb][a_kv[it] * 4 + 2][a_r[it]] = ra[it].z;
                As[nb][a_kv[it] * 4 + 3][a_r[it]] = ra[it].w;
                *(float4*)&Bs[nb][b_kr[it]][b_c4[it] * 4] = rb[it];
            }
        }
        __syncthreads();
    }

    // Store 8x8 microtile to g_M
#pragma unroll
    for (int i = 0; i < 8; i++) {
        float* dst = &g_M[(size_t)(bRow + ty * 8 + i) * NCOL + bCol + tx * 8];
        *(float4*)(dst)     = make_float4(acc[i][0], acc[i][1], acc[i][2], acc[i][3]);
        *(float4*)(dst + 4) = make_float4(acc[i][4], acc[i][5], acc[i][6], acc[i][7]);
    }
}

// ----------------------------------------------------------------------------
// Kernel 2: per-batch pairwise L1 + exp-kernel reduction.
// One CTA (128 threads) per batch row. Thread i owns kernel i.
// ----------------------------------------------------------------------------
__global__ __launch_bounds__(128)
void mbd_pairwise_kernel(float* __restrict__ out)
{
    __shared__ __align__(16) float sM[NCOL];   // 8 KB: this batch row's M

    const int b = blockIdx.x;
    const float* Mb = &g_M[(size_t)b * NCOL];

    // Cooperative copy: 512 float4 / 128 threads = 4 each
#pragma unroll
    for (int it = 0; it < 4; it++) {
        int idx = threadIdx.x + it * 128;    // float4 index 0..511
        *(float4*)&sM[idx * 4] = *(const float4*)&Mb[idx * 4];
    }
    __syncthreads();

    const int i = threadIdx.x;               // kernel index
    float mi[NDIM];
#pragma unroll
    for (int q = 0; q < 4; q++) {
        float4 v = *(const float4*)&sM[i * NDIM + q * 4];
        mi[q * 4 + 0] = v.x; mi[q * 4 + 1] = v.y;
        mi[q * 4 + 2] = v.z; mi[q * 4 + 3] = v.w;
    }

    float acc = 0.0f;
    for (int j = 0; j < NKERN; j++) {
        // 4 partial sums for ILP; sM[j*16+d] is a warp-uniform broadcast read
        float n0 = 0.f, n1 = 0.f, n2 = 0.f, n3 = 0.f;
        const float* mj = &sM[j * NDIM];
#pragma unroll
        for (int d = 0; d < 4; d++) {
            n0 += fabsf(mi[d]      - mj[d]);
            n1 += fabsf(mi[d + 4]  - mj[d + 4]);
            n2 += fabsf(mi[d + 8]  - mj[d + 8]);
            n3 += fabsf(mi[d + 12] - mj[d + 12]);
        }
        acc += __expf(-((n0 + n1) + (n2 + n3)));
    }
    out[(size_t)b * NKERN + i] = acc;
}

// ----------------------------------------------------------------------------
extern "C" void kernel_launch(void* const* d_in, const int* in_sizes, int n_in,
                              void* d_out, int out_size)
{
    const float* x = (const float*)d_in[0];   // [2048, 2048]
    const float* W = (const float*)d_in[1];   // [2048, 2048]
    float* out = (float*)d_out;               // [2048, 128]

    dim3 gemmGrid(NCOL / 128, BATCH / 128);   // (16, 16)
    mbd_sgemm_kernel<<<gemmGrid, 256>>>(x, W);
    mbd_pairwise_kernel<<<BATCH, 128>>>(out);
}

// round 5
// speedup vs baseline: 3.1290x; 3.1290x over previous
#include <cuda_runtime.h>
#include <cuda_bf16.h>
#include <cstdint>

// Problem constants (fixed by setup_inputs)
#define BATCH 2048
#define FDIM  2048
#define NKERN 128
#define NDIM  16
#define NCOL  2048

// __device__ scratch (no allocs allowed)
__device__ float          g_M[BATCH * NCOL];     // GEMM output, fp32
__device__ __nv_bfloat16  g_xb[BATCH * FDIM];    // x in bf16, [M][K] K-major
__device__ __nv_bfloat16  g_wb[NCOL * FDIM];     // W^T in bf16, [N][K] K-major

// ============================================================================
// Conversion kernels
// ============================================================================
__global__ __launch_bounds__(256)
void convert_x_kernel(const float* __restrict__ x) {
    int i = blockIdx.x * blockDim.x + threadIdx.x;   // float4 index
    float4 v = ((const float4*)x)[i];
    __nv_bfloat162 lo = __floats2bfloat162_rn(v.x, v.y);
    __nv_bfloat162 hi = __floats2bfloat162_rn(v.z, v.w);
    uint2 pk;
    pk.x = *(uint32_t*)&lo;
    pk.y = *(uint32_t*)&hi;
    ((uint2*)g_xb)[i] = pk;
}

// W [K][N] fp32  ->  g_wb [N][K] bf16 (tiled transpose)
__global__ __launch_bounds__(256)
void convert_wt_kernel(const float* __restrict__ W) {
    __shared__ float tile[32][33];
    const int n0 = blockIdx.x * 32, k0 = blockIdx.y * 32;
    const int tx = threadIdx.x, ty = threadIdx.y;   // 32 x 8
#pragma unroll
    for (int j = ty; j < 32; j += 8)
        tile[j][tx] = W[(size_t)(k0 + j) * NCOL + n0 + tx];
    __syncthreads();
#pragma unroll
    for (int j = ty; j < 32; j += 8)
        g_wb[(size_t)(n0 + j) * FDIM + k0 + tx] = __float2bfloat16_rn(tile[tx][j]);
}

// ============================================================================
// bf16 mma.sync GEMM: g_M = g_xb @ g_wb^T   (plain-sm_100-safe, no 'a' features)
// 128x128 CTA tile, BK=32, 256 threads (8 warps, 2M x 4N), 3-stage cp.async.
// ============================================================================
#define BK      32
#define STRIDE  40                       // halves per smem row (80 B, conflict-free)
#define STAGE_HALVES (128 * STRIDE)      // per matrix per stage
#define STAGE_BYTES  (2 * STAGE_HALVES * 2)   // A + B
#define NSTAGE  3
#define GEMM_SMEM (NSTAGE * STAGE_BYTES)      // 61440 B

__device__ __forceinline__ void cp_async16(uint32_t dst, const void* src) {
    asm volatile("cp.async.cg.shared.global [%0], [%1], 16;"
                 :: "r"(dst), "l"(src) : "memory");
}
__device__ __forceinline__ void cp_commit() {
    asm volatile("cp.async.commit_group;" ::: "memory");
}
template <int N>
__device__ __forceinline__ void cp_wait() {
    asm volatile("cp.async.wait_group %0;" :: "n"(N) : "memory");
}

__device__ __forceinline__ void ldm_x4(uint32_t addr, uint32_t& r0, uint32_t& r1,
                                       uint32_t& r2, uint32_t& r3) {
    asm volatile("ldmatrix.sync.aligned.m8n8.x4.shared.b16 {%0,%1,%2,%3}, [%4];"
                 : "=r"(r0), "=r"(r1), "=r"(r2), "=r"(r3) : "r"(addr));
}

__device__ __forceinline__ void mma_16816(float* d, const uint32_t* a,
                                          const uint32_t* b) {
    asm volatile(
        "mma.sync.aligned.m16n8k16.row.col.f32.bf16.bf16.f32 "
        "{%0,%1,%2,%3}, {%4,%5,%6,%7}, {%8,%9}, {%0,%1,%2,%3};"
        : "+f"(d[0]), "+f"(d[1]), "+f"(d[2]), "+f"(d[3])
        : "r"(a[0]), "r"(a[1]), "r"(a[2]), "r"(a[3]), "r"(b[0]), "r"(b[1]));
}

// Issue the cp.async loads for one k-chunk into stage buffer `sbase`.
__device__ __forceinline__ void issue_loads(uint32_t sA, uint32_t sB,
                                            int bRow, int bCol, int k0, int tid) {
#pragma unroll
    for (int i = 0; i < 2; i++) {
        int id  = tid * 2 + i;           // 0..511
        int row = id >> 2;               // 0..127
        int c   = id & 3;                // 16B chunk within 64B row
        uint32_t off = row * (STRIDE * 2) + c * 16;
        cp_async16(sA + off, g_xb + (size_t)(bRow + row) * FDIM + k0 + c * 8);
        cp_async16(sB + off, g_wb + (size_t)(bCol + row) * FDIM + k0 + c * 8);
    }
}

__global__ __launch_bounds__(256, 2)
void mbd_mma_gemm() {
    extern __shared__ __align__(128) char smem[];
    const uint32_t sbase = (uint32_t)__cvta_generic_to_shared(smem);

    const int tid  = threadIdx.x;
    const int wid  = tid >> 5;
    const int lane = tid & 31;
    const int bRow = blockIdx.y * 128;
    const int bCol = blockIdx.x * 128;
    const int wm   = (wid & 1) * 64;     // warp M offset in tile
    const int wn   = (wid >> 1) * 32;    // warp N offset in tile

    uint32_t stA[NSTAGE], stB[NSTAGE];
#pragma unroll
    for (int s = 0; s < NSTAGE; s++) {
        stA[s] = sbase + s * STAGE_BYTES;
        stB[s] = stA[s] + STAGE_HALVES * 2;
    }

    float acc[4][4][4];
#pragma unroll
    for (int i = 0; i < 4; i++)
#pragma unroll
        for (int j = 0; j < 4; j++)
#pragma unroll
            for (int q = 0; q < 4; q++) acc[i][j][q] = 0.0f;

    // Prologue: stages 0 and 1 in flight
    issue_loads(stA[0], stB[0], bRow, bCol, 0, tid);
    cp_commit();
    issue_loads(stA[1], stB[1], bRow, bCol, BK, tid);
    cp_commit();

    // Per-thread ldmatrix source offsets (within a stage buffer, in bytes):
    // A x4 (one 16-row m-frag, full k16): rows lane&15, k-half sel lane>>4
    const uint32_t aoff = (uint32_t)((lane & 15) * STRIDE + (lane >> 4) * 8) * 2;
    // B x4 (two 8-col n-frags, full k16): rows (lane>>4)*8 + (lane&7), k-half (lane>>3)&1
    const uint32_t boff = (uint32_t)(((lane >> 4) * 8 + (lane & 7)) * STRIDE
                                     + ((lane >> 3) & 1) * 8) * 2;

    const int T = FDIM / BK;             // 64
#pragma unroll 1
    for (int t = 0; t < T; t++) {
        cp_wait<NSTAGE - 2>();           // stage t resident
        __syncthreads();                 // also fences stage (t+2)%3 reuse

        if (t + 2 < T) {
            int s = (t + 2) % NSTAGE;
            issue_loads(stA[s], stB[s], bRow, bCol, (t + 2) * BK, tid);
        }
        cp_commit();                     // keep group count in lockstep

        const int cs = t % NSTAGE;
        const uint32_t cA = stA[cs] + aoff;
        const uint32_t cB = stB[cs] + boff;

#pragma unroll
        for (int ks = 0; ks < 2; ks++) {
            uint32_t a[4][4], b[2][4];
#pragma unroll
            for (int mf = 0; mf < 4; mf++)
                ldm_x4(cA + ((mf + (wm >> 4)) * 16 * STRIDE + ks * 16) * 2,
                       a[mf][0], a[mf][1], a[mf][2], a[mf][3]);
#pragma unroll
            for (int p = 0; p < 2; p++)
                ldm_x4(cB + ((wn + p * 16) * STRIDE + ks * 16) * 2,
                       b[p][0], b[p][1], b[p][2], b[p][3]);
#pragma unroll
            for (int mf = 0; mf < 4; mf++) {
#pragma unroll
                for (int nf = 0; nf < 4; nf++) {
                    const uint32_t* bf = &b[nf >> 1][(nf & 1) * 2];
                    mma_16816(acc[mf][nf], a[mf], bf);
                }
            }
        }
    }

    // Epilogue: per-thread fragment scatter to g_M
    const int r0 = bRow + wm + (lane >> 2);
    const int c0 = bCol + wn + (lane & 3) * 2;
#pragma unroll
    for (int mf = 0; mf < 4; mf++) {
#pragma unroll
        for (int nf = 0; nf < 4; nf++) {
            float* d0 = &g_M[(size_t)(r0 + mf * 16)     * NCOL + c0 + nf * 8];
            float* d1 = &g_M[(size_t)(r0 + mf * 16 + 8) * NCOL + c0 + nf * 8];
            *(float2*)d0 = make_float2(acc[mf][nf][0], acc[mf][nf][1]);
            *(float2*)d1 = make_float2(acc[mf][nf][2], acc[mf][nf][3]);
        }
    }
}

// ============================================================================
// Kernel 2: per-batch pairwise L1 + exp-kernel reduction (unchanged, proven)
// ============================================================================
__global__ __launch_bounds__(128)
void mbd_pairwise_kernel(float* __restrict__ out)
{
    __shared__ __align__(16) float sM[NCOL];

    const int b = blockIdx.x;
    const float* Mb = &g_M[(size_t)b * NCOL];

#pragma unroll
    for (int it = 0; it < 4; it++) {
        int idx = threadIdx.x + it * 128;
        *(float4*)&sM[idx * 4] = *(const float4*)&Mb[idx * 4];
    }
    __syncthreads();

    const int i = threadIdx.x;
    float mi[NDIM];
#pragma unroll
    for (int q = 0; q < 4; q++) {
        float4 v = *(const float4*)&sM[i * NDIM + q * 4];
        mi[q * 4 + 0] = v.x; mi[q * 4 + 1] = v.y;
        mi[q * 4 + 2] = v.z; mi[q * 4 + 3] = v.w;
    }

    float acc = 0.0f;
    for (int j = 0; j < NKERN; j++) {
        float n0 = 0.f, n1 = 0.f, n2 = 0.f, n3 = 0.f;
        const float* mj = &sM[j * NDIM];
#pragma unroll
        for (int d = 0; d < 4; d++) {
            n0 += fabsf(mi[d]      - mj[d]);
            n1 += fabsf(mi[d + 4]  - mj[d + 4]);
            n2 += fabsf(mi[d + 8]  - mj[d + 8]);
            n3 += fabsf(mi[d + 12] - mj[d + 12]);
        }
        acc += __expf(-((n0 + n1) + (n2 + n3)));
    }
    out[(size_t)b * NKERN + i] = acc;
}

// ============================================================================
extern "C" void kernel_launch(void* const* d_in, const int* in_sizes, int n_in,
                              void* d_out, int out_size)
{
    const float* x = (const float*)d_in[0];   // [2048, 2048]
    const float* W = (const float*)d_in[1];   // [2048, 2048]
    float* out = (float*)d_out;               // [2048, 128]

    convert_x_kernel<<<(BATCH * FDIM / 4) / 256, 256>>>(x);
    convert_wt_kernel<<<dim3(NCOL / 32, FDIM / 32), dim3(32, 8)>>>(W);

    cudaFuncSetAttribute(mbd_mma_gemm,
                         cudaFuncAttributeMaxDynamicSharedMemorySize, GEMM_SMEM);
    mbd_mma_gemm<<<dim3(NCOL / 128, BATCH / 128), 256, GEMM_SMEM>>>();

    mbd_pairwise_kernel<<<BATCH, 128>>>(out);
}

// round 8
// speedup vs baseline: 3.2211x; 1.0295x over previous
#include <cuda_runtime.h>
#include <cuda_bf16.h>
#include <cuda_fp16.h>
#include <cstdint>

// Problem constants (fixed by setup_inputs)
#define BATCH 2048
#define FDIM  2048
#define NKERN 128
#define NDIM  16
#define NCOL  2048

// __device__ scratch (no allocs allowed)
__device__ float          g_M[BATCH * NCOL];     // GEMM output, fp32
__device__ __nv_bfloat16  g_xb[BATCH * FDIM];    // x in bf16, [M][K] K-major
__device__ __nv_bfloat16  g_wb[NCOL * FDIM];     // W^T in bf16, [N][K] K-major

// ============================================================================
// Conversion kernels
// ============================================================================
__global__ __launch_bounds__(256)
void convert_x_kernel(const float* __restrict__ x) {
    int i = blockIdx.x * blockDim.x + threadIdx.x;   // float4 index
    float4 v = ((const float4*)x)[i];
    __nv_bfloat162 lo = __floats2bfloat162_rn(v.x, v.y);
    __nv_bfloat162 hi = __floats2bfloat162_rn(v.z, v.w);
    uint2 pk;
    pk.x = *(uint32_t*)&lo;
    pk.y = *(uint32_t*)&hi;
    ((uint2*)g_xb)[i] = pk;
}

// W [K][N] fp32  ->  g_wb [N][K] bf16 (tiled transpose)
__global__ __launch_bounds__(256)
void convert_wt_kernel(const float* __restrict__ W) {
    __shared__ float tile[32][33];
    const int n0 = blockIdx.x * 32, k0 = blockIdx.y * 32;
    const int tx = threadIdx.x, ty = threadIdx.y;   // 32 x 8
#pragma unroll
    for (int j = ty; j < 32; j += 8)
        tile[j][tx] = W[(size_t)(k0 + j) * NCOL + n0 + tx];
    __syncthreads();
#pragma unroll
    for (int j = ty; j < 32; j += 8)
        g_wb[(size_t)(n0 + j) * FDIM + k0 + tx] = __float2bfloat16_rn(tile[tx][j]);
}

// ============================================================================
// bf16 mma.sync GEMM: g_M = g_xb @ g_wb^T   (plain-sm_100-safe, no 'a' features)
// 128x128 CTA tile, BK=32, 256 threads (8 warps, 2M x 4N), 4-stage cp.async.
// ============================================================================
#define BK      32
#define STRIDE  40                       // halves per smem row (80 B, conflict-free)
#define STAGE_HALVES (128 * STRIDE)      // per matrix per stage
#define STAGE_BYTES  (2 * STAGE_HALVES * 2)   // A + B
#define NSTAGE  4
#define GEMM_SMEM (NSTAGE * STAGE_BYTES)      // 81920 B

__device__ __forceinline__ void cp_async16(uint32_t dst, const void* src) {
    asm volatile("cp.async.cg.shared.global [%0], [%1], 16;"
                 :: "r"(dst), "l"(src) : "memory");
}
__device__ __forceinline__ void cp_commit() {
    asm volatile("cp.async.commit_group;" ::: "memory");
}
template <int N>
__device__ __forceinline__ void cp_wait() {
    asm volatile("cp.async.wait_group %0;" :: "n"(N) : "memory");
}

__device__ __forceinline__ void ldm_x4(uint32_t addr, uint32_t& r0, uint32_t& r1,
                                       uint32_t& r2, uint32_t& r3) {
    asm volatile("ldmatrix.sync.aligned.m8n8.x4.shared.b16 {%0,%1,%2,%3}, [%4];"
                 : "=r"(r0), "=r"(r1), "=r"(r2), "=r"(r3) : "r"(addr));
}

__device__ __forceinline__ void mma_16816(float* d, const uint32_t* a,
                                          const uint32_t* b) {
    asm volatile(
        "mma.sync.aligned.m16n8k16.row.col.f32.bf16.bf16.f32 "
        "{%0,%1,%2,%3}, {%4,%5,%6,%7}, {%8,%9}, {%0,%1,%2,%3};"
        : "+f"(d[0]), "+f"(d[1]), "+f"(d[2]), "+f"(d[3])
        : "r"(a[0]), "r"(a[1]), "r"(a[2]), "r"(a[3]), "r"(b[0]), "r"(b[1]));
}

// Issue the cp.async loads for one k-chunk into stage buffer `sbase`.
__device__ __forceinline__ void issue_loads(uint32_t sA, uint32_t sB,
                                            int bRow, int bCol, int k0, int tid) {
#pragma unroll
    for (int i = 0; i < 2; i++) {
        int id  = tid * 2 + i;           // 0..511
        int row = id >> 2;               // 0..127
        int c   = id & 3;                // 16B chunk within 64B row
        uint32_t off = row * (STRIDE * 2) + c * 16;
        cp_async16(sA + off, g_xb + (size_t)(bRow + row) * FDIM + k0 + c * 8);
        cp_async16(sB + off, g_wb + (size_t)(bCol + row) * FDIM + k0 + c * 8);
    }
}

__global__ __launch_bounds__(256, 2)
void mbd_mma_gemm() {
    extern __shared__ __align__(128) char smem[];
    const uint32_t sbase = (uint32_t)__cvta_generic_to_shared(smem);

    const int tid  = threadIdx.x;
    const int wid  = tid >> 5;
    const int lane = tid & 31;
    const int bRow = blockIdx.y * 128;
    const int bCol = blockIdx.x * 128;
    const int wm   = (wid & 1) * 64;     // warp M offset in tile
    const int wn   = (wid >> 1) * 32;    // warp N offset in tile

    uint32_t stA[NSTAGE], stB[NSTAGE];
#pragma unroll
    for (int s = 0; s < NSTAGE; s++) {
        stA[s] = sbase + s * STAGE_BYTES;
        stB[s] = stA[s] + STAGE_HALVES * 2;
    }

    float acc[4][4][4];
#pragma unroll
    for (int i = 0; i < 4; i++)
#pragma unroll
        for (int j = 0; j < 4; j++)
#pragma unroll
            for (int q = 0; q < 4; q++) acc[i][j][q] = 0.0f;

    // Prologue: stages 0..2 in flight
#pragma unroll
    for (int s = 0; s < NSTAGE - 1; s++) {
        issue_loads(stA[s], stB[s], bRow, bCol, s * BK, tid);
        cp_commit();
    }

    // Per-thread ldmatrix source offsets (within a stage buffer, in bytes):
    const uint32_t aoff = (uint32_t)((lane & 15) * STRIDE + (lane >> 4) * 8) * 2;
    const uint32_t boff = (uint32_t)(((lane >> 4) * 8 + (lane & 7)) * STRIDE
                                     + ((lane >> 3) & 1) * 8) * 2;

    const int T = FDIM / BK;             // 64
#pragma unroll 1
    for (int t = 0; t < T; t++) {
        cp_wait<NSTAGE - 2>();           // stage t resident
        __syncthreads();                 // also fences slot reuse

        if (t + NSTAGE - 1 < T) {
            int s = (t + NSTAGE - 1) % NSTAGE;
            issue_loads(stA[s], stB[s], bRow, bCol, (t + NSTAGE - 1) * BK, tid);
        }
        cp_commit();                     // keep group count in lockstep

        const int cs = t % NSTAGE;
        const uint32_t cA = stA[cs] + aoff;
        const uint32_t cB = stB[cs] + boff;

#pragma unroll
        for (int ks = 0; ks < 2; ks++) {
            uint32_t a[4][4], b[2][4];
#pragma unroll
            for (int mf = 0; mf < 4; mf++)
                ldm_x4(cA + ((mf + (wm >> 4)) * 16 * STRIDE + ks * 16) * 2,
                       a[mf][0], a[mf][1], a[mf][2], a[mf][3]);
#pragma unroll
            for (int p = 0; p < 2; p++)
                ldm_x4(cB + ((wn + p * 16) * STRIDE + ks * 16) * 2,
                       b[p][0], b[p][1], b[p][2], b[p][3]);
#pragma unroll
            for (int mf = 0; mf < 4; mf++) {
#pragma unroll
                for (int nf = 0; nf < 4; nf++) {
                    const uint32_t* bf = &b[nf >> 1][(nf & 1) * 2];
                    mma_16816(acc[mf][nf], a[mf], bf);
                }
            }
        }
    }

    // Epilogue: per-thread fragment scatter to g_M
    const int r0 = bRow + wm + (lane >> 2);
    const int c0 = bCol + wn + (lane & 3) * 2;
#pragma unroll
    for (int mf = 0; mf < 4; mf++) {
#pragma unroll
        for (int nf = 0; nf < 4; nf++) {
            float* d0 = &g_M[(size_t)(r0 + mf * 16)     * NCOL + c0 + nf * 8];
            float* d1 = &g_M[(size_t)(r0 + mf * 16 + 8) * NCOL + c0 + nf * 8];
            *(float2*)d0 = make_float2(acc[mf][nf][0], acc[mf][nf][1]);
            *(float2*)d1 = make_float2(acc[mf][nf][2], acc[mf][nf][3]);
        }
    }
}

// ============================================================================
// Kernel 2: per-batch pairwise L1 + exp via packed half2 math.
// One CTA (128 threads) per batch row; thread i owns kernel i.
// fma-pipe ops per j drop ~35 -> ~18; abs goes to alu pipe; 2 LDS.128 per j.
// ============================================================================
__global__ __launch_bounds__(128)
void mbd_pairwise_kernel(float* __restrict__ out)
{
    __shared__ __align__(16) __half2 sMh[NKERN * 8];   // 128 kernels x 16 dims, 4 KB

    const int b = blockIdx.x;
    const float* Mb = &g_M[(size_t)b * NCOL];

    // Load + convert: 512 float4 -> 1024 half2; 4 float4 per thread.
#pragma unroll
    for (int it = 0; it < 4; it++) {
        int idx = threadIdx.x + it * 128;              // float4 index 0..511
        float4 v = *(const float4*)&Mb[idx * 4];
        sMh[idx * 2 + 0] = __floats2half2_rn(v.x, v.y);
        sMh[idx * 2 + 1] = __floats2half2_rn(v.z, v.w);
    }
    __syncthreads();

    const int i = threadIdx.x;
    __half2 mi[8];
#pragma unroll
    for (int q = 0; q < 8; q++) mi[q] = sMh[i * 8 + q];

    float acc = 0.0f;
#pragma unroll 4
    for (int j = 0; j < NKERN; j++) {
        // mj: 8 half2 = 32 B, two LDS.128 broadcast reads
        uint4 u0 = *(const uint4*)&sMh[j * 8];
        uint4 u1 = *(const uint4*)&sMh[j * 8 + 4];
        __half2 m0 = *(__half2*)&u0.x, m1 = *(__half2*)&u0.y;
        __half2 m2 = *(__half2*)&u0.z, m3 = *(__half2*)&u0.w;
        __half2 m4 = *(__half2*)&u1.x, m5 = *(__half2*)&u1.y;
        __half2 m6 = *(__half2*)&u1.z, m7 = *(__half2*)&u1.w;

        __half2 d0 = __habs2(__hsub2(mi[0], m0));
        __half2 d1 = __habs2(__hsub2(mi[1], m1));
        __half2 d2 = __habs2(__hsub2(mi[2], m2));
        __half2 d3 = __habs2(__hsub2(mi[3], m3));
        __half2 d4 = __habs2(__hsub2(mi[4], m4));
        __half2 d5 = __habs2(__hsub2(mi[5], m5));
        __half2 d6 = __habs2(__hsub2(mi[6], m6));
        __half2 d7 = __habs2(__hsub2(mi[7], m7));

        __half2 e0 = __hadd2(d0, d1);
        __half2 e1 = __hadd2(d2, d3);
        __half2 e2 = __hadd2(d4, d5);
        __half2 e3 = __hadd2(d6, d7);
        __half2 f0 = __hadd2(e0, e1);
        __half2 f1 = __hadd2(e2, e3);
        __half2 s  = __hadd2(f0, f1);

        float2 fs = __half22float2(s);
        acc += __expf(-(fs.x + fs.y));
    }
    out[(size_t)b * NKERN + i] = acc;
}

// ============================================================================
extern "C" void kernel_launch(void* const* d_in, const int* in_sizes, int n_in,
                              void* d_out, int out_size)
{
    const float* x = (const float*)d_in[0];   // [2048, 2048]
    const float* W = (const float*)d_in[1];   // [2048, 2048]
    float* out = (float*)d_out;               // [2048, 128]

    convert_x_kernel<<<(BATCH * FDIM / 4) / 256, 256>>>(x);
    convert_wt_kernel<<<dim3(NCOL / 32, FDIM / 32), dim3(32, 8)>>>(W);

    cudaFuncSetAttribute(mbd_mma_gemm,
                         cudaFuncAttributeMaxDynamicSharedMemorySize, GEMM_SMEM);
    mbd_mma_gemm<<<dim3(NCOL / 128, BATCH / 128), 256, GEMM_SMEM>>>();

    mbd_pairwise_kernel<<<BATCH, 128>>>(out);
}

// round 9
// speedup vs baseline: 3.5841x; 1.1127x over previous
#include <cuda_runtime.h>
#include <cuda_bf16.h>
#include <cuda_fp16.h>
#include <cstdint>

// Problem constants (fixed by setup_inputs)
#define BATCH 2048
#define FDIM  2048
#define NKERN 128
#define NDIM  16
#define NCOL  2048

#define LOG2E 1.4426950408889634f

// __device__ scratch (no allocs allowed)
__device__ __half         g_Mh[BATCH * NCOL];    // M * log2e, fp16 (8 MB)
__device__ __nv_bfloat16  g_xb[BATCH * FDIM];    // x in bf16, [M][K] K-major
__device__ __nv_bfloat16  g_wb[NCOL * FDIM];     // W^T in bf16, [N][K] K-major

// ============================================================================
// Conversion kernels
// ============================================================================
__global__ __launch_bounds__(256)
void convert_x_kernel(const float* __restrict__ x) {
    int i = blockIdx.x * blockDim.x + threadIdx.x;   // float4 index
    float4 v = ((const float4*)x)[i];
    __nv_bfloat162 lo = __floats2bfloat162_rn(v.x, v.y);
    __nv_bfloat162 hi = __floats2bfloat162_rn(v.z, v.w);
    uint2 pk;
    pk.x = *(uint32_t*)&lo;
    pk.y = *(uint32_t*)&hi;
    ((uint2*)g_xb)[i] = pk;
}

// W [K][N] fp32  ->  g_wb [N][K] bf16 (tiled transpose)
__global__ __launch_bounds__(256)
void convert_wt_kernel(const float* __restrict__ W) {
    __shared__ float tile[32][33];
    const int n0 = blockIdx.x * 32, k0 = blockIdx.y * 32;
    const int tx = threadIdx.x, ty = threadIdx.y;   // 32 x 8
#pragma unroll
    for (int j = ty; j < 32; j += 8)
        tile[j][tx] = W[(size_t)(k0 + j) * NCOL + n0 + tx];
    __syncthreads();
#pragma unroll
    for (int j = ty; j < 32; j += 8)
        g_wb[(size_t)(n0 + j) * FDIM + k0 + tx] = __float2bfloat16_rn(tile[tx][j]);
}

// ============================================================================
// bf16 mma.sync GEMM: M = g_xb @ g_wb^T, epilogue stores M*log2e as fp16.
// 128x128 CTA tile, BK=32, 256 threads (8 warps, 2M x 4N), 3-stage cp.async.
// ============================================================================
#define BK      32
#define STRIDE  40                       // halves per smem row (80 B, conflict-free)
#define STAGE_HALVES (128 * STRIDE)      // per matrix per stage
#define STAGE_BYTES  (2 * STAGE_HALVES * 2)   // A + B
#define NSTAGE  3
#define GEMM_SMEM (NSTAGE * STAGE_BYTES)      // 61440 B

__device__ __forceinline__ void cp_async16(uint32_t dst, const void* src) {
    asm volatile("cp.async.cg.shared.global [%0], [%1], 16;"
                 :: "r"(dst), "l"(src) : "memory");
}
__device__ __forceinline__ void cp_commit() {
    asm volatile("cp.async.commit_group;" ::: "memory");
}
template <int N>
__device__ __forceinline__ void cp_wait() {
    asm volatile("cp.async.wait_group %0;" :: "n"(N) : "memory");
}

__device__ __forceinline__ void ldm_x4(uint32_t addr, uint32_t& r0, uint32_t& r1,
                                       uint32_t& r2, uint32_t& r3) {
    asm volatile("ldmatrix.sync.aligned.m8n8.x4.shared.b16 {%0,%1,%2,%3}, [%4];"
                 : "=r"(r0), "=r"(r1), "=r"(r2), "=r"(r3) : "r"(addr));
}

__device__ __forceinline__ void mma_16816(float* d, const uint32_t* a,
                                          const uint32_t* b) {
    asm volatile(
        "mma.sync.aligned.m16n8k16.row.col.f32.bf16.bf16.f32 "
        "{%0,%1,%2,%3}, {%4,%5,%6,%7}, {%8,%9}, {%0,%1,%2,%3};"
        : "+f"(d[0]), "+f"(d[1]), "+f"(d[2]), "+f"(d[3])
        : "r"(a[0]), "r"(a[1]), "r"(a[2]), "r"(a[3]), "r"(b[0]), "r"(b[1]));
}

// Issue the cp.async loads for one k-chunk into stage buffer `sbase`.
__device__ __forceinline__ void issue_loads(uint32_t sA, uint32_t sB,
                                            int bRow, int bCol, int k0, int tid) {
#pragma unroll
    for (int i = 0; i < 2; i++) {
        int id  = tid * 2 + i;           // 0..511
        int row = id >> 2;               // 0..127
        int c   = id & 3;                // 16B chunk within 64B row
        uint32_t off = row * (STRIDE * 2) + c * 16;
        cp_async16(sA + off, g_xb + (size_t)(bRow + row) * FDIM + k0 + c * 8);
        cp_async16(sB + off, g_wb + (size_t)(bCol + row) * FDIM + k0 + c * 8);
    }
}

__global__ __launch_bounds__(256, 2)
void mbd_mma_gemm() {
    extern __shared__ __align__(128) char smem[];
    const uint32_t sbase = (uint32_t)__cvta_generic_to_shared(smem);

    const int tid  = threadIdx.x;
    const int wid  = tid >> 5;
    const int lane = tid & 31;
    const int bRow = blockIdx.y * 128;
    const int bCol = blockIdx.x * 128;
    const int wm   = (wid & 1) * 64;     // warp M offset in tile
    const int wn   = (wid >> 1) * 32;    // warp N offset in tile

    uint32_t stA[NSTAGE], stB[NSTAGE];
#pragma unroll
    for (int s = 0; s < NSTAGE; s++) {
        stA[s] = sbase + s * STAGE_BYTES;
        stB[s] = stA[s] + STAGE_HALVES * 2;
    }

    float acc[4][4][4];
#pragma unroll
    for (int i = 0; i < 4; i++)
#pragma unroll
        for (int j = 0; j < 4; j++)
#pragma unroll
            for (int q = 0; q < 4; q++) acc[i][j][q] = 0.0f;

    // Prologue: stages 0..NSTAGE-2 in flight
#pragma unroll
    for (int s = 0; s < NSTAGE - 1; s++) {
        issue_loads(stA[s], stB[s], bRow, bCol, s * BK, tid);
        cp_commit();
    }

    // Per-thread ldmatrix source offsets (within a stage buffer, in bytes):
    const uint32_t aoff = (uint32_t)((lane & 15) * STRIDE + (lane >> 4) * 8) * 2;
    const uint32_t boff = (uint32_t)(((lane >> 4) * 8 + (lane & 7)) * STRIDE
                                     + ((lane >> 3) & 1) * 8) * 2;

    const int T = FDIM / BK;             // 64
#pragma unroll 1
    for (int t = 0; t < T; t++) {
        cp_wait<NSTAGE - 2>();           // stage t resident
        __syncthreads();                 // also fences slot reuse

        if (t + NSTAGE - 1 < T) {
            int s = (t + NSTAGE - 1) % NSTAGE;
            issue_loads(stA[s], stB[s], bRow, bCol, (t + NSTAGE - 1) * BK, tid);
        }
        cp_commit();                     // keep group count in lockstep

        const int cs = t % NSTAGE;
        const uint32_t cA = stA[cs] + aoff;
        const uint32_t cB = stB[cs] + boff;

#pragma unroll
        for (int ks = 0; ks < 2; ks++) {
            uint32_t a[4][4], b[2][4];
#pragma unroll
            for (int mf = 0; mf < 4; mf++)
                ldm_x4(cA + ((mf + (wm >> 4)) * 16 * STRIDE + ks * 16) * 2,
                       a[mf][0], a[mf][1], a[mf][2], a[mf][3]);
#pragma unroll
            for (int p = 0; p < 2; p++)
                ldm_x4(cB + ((wn + p * 16) * STRIDE + ks * 16) * 2,
                       b[p][0], b[p][1], b[p][2], b[p][3]);
#pragma unroll
            for (int mf = 0; mf < 4; mf++) {
#pragma unroll
                for (int nf = 0; nf < 4; nf++) {
                    const uint32_t* bf = &b[nf >> 1][(nf & 1) * 2];
                    mma_16816(acc[mf][nf], a[mf], bf);
                }
            }
        }
    }

    // Epilogue: scale by log2e, pack to fp16, store 32-bit pairs to g_Mh.
    // Thread owns cols (c0, c0+1) with c0 even -> aligned 4B stores.
    const int r0 = bRow + wm + (lane >> 2);
    const int c0 = bCol + wn + (lane & 3) * 2;
#pragma unroll
    for (int mf = 0; mf < 4; mf++) {
#pragma unroll
        for (int nf = 0; nf < 4; nf++) {
            __half2 p01 = __floats2half2_rn(acc[mf][nf][0] * LOG2E,
                                            acc[mf][nf][1] * LOG2E);
            __half2 p23 = __floats2half2_rn(acc[mf][nf][2] * LOG2E,
                                            acc[mf][nf][3] * LOG2E);
            *(uint32_t*)&g_Mh[(size_t)(r0 + mf * 16)     * NCOL + c0 + nf * 8] =
                *(uint32_t*)&p01;
            *(uint32_t*)&g_Mh[(size_t)(r0 + mf * 16 + 8) * NCOL + c0 + nf * 8] =
                *(uint32_t*)&p23;
        }
    }
}

// ============================================================================
// Kernel 2: per-batch pairwise L1 + exp2 via packed half2 math.
// M already scaled by log2e -> exp(-norm) = exp2(-norm_scaled).
// ============================================================================
__global__ __launch_bounds__(128)
void mbd_pairwise_kernel(float* __restrict__ out)
{
    __shared__ __align__(16) __half2 sMh[NKERN * 8];   // 4 KB

    const int b = blockIdx.x;
    const uint4* Mb = (const uint4*)&g_Mh[(size_t)b * NCOL];

    // Copy 4 KB row: 256 uint4 / 128 threads = 2 each
    ((uint4*)sMh)[threadIdx.x]       = Mb[threadIdx.x];
    ((uint4*)sMh)[threadIdx.x + 128] = Mb[threadIdx.x + 128];
    __syncthreads();

    const int i = threadIdx.x;
    __half2 mi[8];
#pragma unroll
    for (int q = 0; q < 8; q++) mi[q] = sMh[i * 8 + q];

    float acc = 0.0f;
#pragma unroll 4
    for (int j = 0; j < NKERN; j++) {
        uint4 u0 = *(const uint4*)&sMh[j * 8];
        uint4 u1 = *(const uint4*)&sMh[j * 8 + 4];
        __half2 m0 = *(__half2*)&u0.x, m1 = *(__half2*)&u0.y;
        __half2 m2 = *(__half2*)&u0.z, m3 = *(__half2*)&u0.w;
        __half2 m4 = *(__half2*)&u1.x, m5 = *(__half2*)&u1.y;
        __half2 m6 = *(__half2*)&u1.z, m7 = *(__half2*)&u1.w;

        __half2 d0 = __habs2(__hsub2(mi[0], m0));
        __half2 d1 = __habs2(__hsub2(mi[1], m1));
        __half2 d2 = __habs2(__hsub2(mi[2], m2));
        __half2 d3 = __habs2(__hsub2(mi[3], m3));
        __half2 d4 = __habs2(__hsub2(mi[4], m4));
        __half2 d5 = __habs2(__hsub2(mi[5], m5));
        __half2 d6 = __habs2(__hsub2(mi[6], m6));
        __half2 d7 = __habs2(__hsub2(mi[7], m7));

        __half2 e0 = __hadd2(d0, d1);
        __half2 e1 = __hadd2(d2, d3);
        __half2 e2 = __hadd2(d4, d5);
        __half2 e3 = __hadd2(d6, d7);
        __half2 f0 = __hadd2(e0, e1);
        __half2 f1 = __hadd2(e2, e3);
        __half2 s  = __hadd2(f0, f1);

        __half  hs = __hadd(__low2half(s), __high2half(s));
        float   nf = -__half2float(hs);
        float   e;
        asm("ex2.approx.ftz.f32 %0, %1;" : "=f"(e) : "f"(nf));
        acc += e;
    }
    out[(size_t)b * NKERN + i] = acc;
}

// ============================================================================
extern "C" void kernel_launch(void* const* d_in, const int* in_sizes, int n_in,
                              void* d_out, int out_size)
{
    const float* x = (const float*)d_in[0];   // [2048, 2048]
    const float* W = (const float*)d_in[1];   // [2048, 2048]
    float* out = (float*)d_out;               // [2048, 128]

    convert_x_kernel<<<(BATCH * FDIM / 4) / 256, 256>>>(x);
    convert_wt_kernel<<<dim3(NCOL / 32, FDIM / 32), dim3(32, 8)>>>(W);

    cudaFuncSetAttribute(mbd_mma_gemm,
                         cudaFuncAttributeMaxDynamicSharedMemorySize, GEMM_SMEM);
    mbd_mma_gemm<<<dim3(NCOL / 128, BATCH / 128), 256, GEMM_SMEM>>>();

    mbd_pairwise_kernel<<<BATCH, 128>>>(out);
}